// round 7
// baseline (speedup 1.0000x reference)
#include <cuda_runtime.h>
#include <cuda_bf16.h>

#define EPSF 1e-6f
#define TWO_PI_F 6.283185307179586f
#define NB_BASE 32
#define TPB 128            // 4 warps per block
#define EV_PER_BLK 4       // one event per warp

// Scratch (no device allocation allowed)
__device__ float g_ev[8192];       // per-event A_i * B_i
__device__ float g_base[NB_BASE];  // per-block base-rate partial sums
__device__ int   g_count = 0;      // arrival counter (reset by last block)

// ---------------------------------------------------------------------------
// Single fused kernel.
//   blocks [0, NB_BASE)                 : base-rate grid partial sums
//   blocks [NB_BASE, NB_BASE + N/4)     : 4 events per block, one per WARP
// Last block to arrive does the final deterministic reduction -> out[N].
// ---------------------------------------------------------------------------
__global__ __launch_bounds__(TPB) void k_fused(
    const float* __restrict__ x, const float* __restrict__ t,
    const float* __restrict__ past_x, const float* __restrict__ past_t,
    const float* __restrict__ cov,
    const float* __restrict__ z, const float* __restrict__ x_grid,
    const float* __restrict__ t_grid, const float* __restrict__ beta,
    const float* __restrict__ p_alpha, const float* __restrict__ p_sigma,
    const float* __restrict__ p_omega,
    int N, int M, int G, int T, int D, int rows,
    float* __restrict__ out)
{
    __shared__ float smS[4], smB[4];
    __shared__ int   sm_last;
    const int tid  = threadIdx.x;
    const int warp = tid >> 5;
    const int lane = tid & 31;

    const float alpha = *p_alpha;
    const float sigma = *p_sigma;
    const float omega = *p_omega;
    const float inv2s2 = 1.0f / (2.0f * sigma * sigma);
    const float Cf     = alpha * omega / (TWO_PI_F * sigma * sigma);

    if (blockIdx.x < (unsigned)NB_BASE) {
        // ================= base-rate partial blocks =================
        const int bj = blockIdx.x;
        float bta[16];
        #pragma unroll
        for (int d = 0; d < 16; d++) bta[d] = (d < D) ? beta[d] : 0.0f;

        float s = 0.0f;
        if (D == 16) {
            for (int r = bj * TPB + tid; r < rows; r += NB_BASE * TPB) {
                const float4* __restrict__ zr =
                    reinterpret_cast<const float4*>(z + (size_t)r * 16);
                float4 v0 = zr[0], v1 = zr[1], v2 = zr[2], v3 = zr[3];
                float dot = 0.0f;
                dot = fmaf(v0.x, bta[0],  dot); dot = fmaf(v0.y, bta[1],  dot);
                dot = fmaf(v0.z, bta[2],  dot); dot = fmaf(v0.w, bta[3],  dot);
                dot = fmaf(v1.x, bta[4],  dot); dot = fmaf(v1.y, bta[5],  dot);
                dot = fmaf(v1.z, bta[6],  dot); dot = fmaf(v1.w, bta[7],  dot);
                dot = fmaf(v2.x, bta[8],  dot); dot = fmaf(v2.y, bta[9],  dot);
                dot = fmaf(v2.z, bta[10], dot); dot = fmaf(v2.w, bta[11], dot);
                dot = fmaf(v3.x, bta[12], dot); dot = fmaf(v3.y, bta[13], dot);
                dot = fmaf(v3.z, bta[14], dot); dot = fmaf(v3.w, bta[15], dot);
                s += fmaxf(dot, EPSF);
            }
        } else {
            for (int r = bj * TPB + tid; r < rows; r += NB_BASE * TPB) {
                float dot = 0.0f;
                for (int d = 0; d < D; d++)
                    dot = fmaf(z[(size_t)r * D + d], beta[d], dot);
                s += fmaxf(dot, EPSF);
            }
        }
        #pragma unroll
        for (int o = 16; o > 0; o >>= 1)
            s += __shfl_down_sync(0xffffffffu, s, o);
        if (lane == 0) smS[warp] = s;
        __syncthreads();
        if (tid == 0) {
            float S = smS[0] + smS[1] + smS[2] + smS[3];
            g_base[bj] = S;
        }
    } else {
        // ================= event warps (one event per warp) =================
        const int i = (blockIdx.x - NB_BASE) * EV_PER_BLK + warp;

        const float xi = x[2 * i];
        const float yi = x[2 * i + 1];
        const float ti = t[i];

        const float4* __restrict__ pt4 =
            reinterpret_cast<const float4*>(past_t + (size_t)i * M);
        const float4* __restrict__ px4 =
            reinterpret_cast<const float4*>(past_x + (size_t)i * 2 * M);

        float s = 0.0f;

        if (M == 2048) {
            // 512 float4 time-slots, 16 per lane; unroll 4 keeps ~12 LDG.128
            // in flight per lane continuously.
            #pragma unroll 4
            for (int it = 0; it < 16; it++) {
                const int sl = it * 32 + lane;
                float4 tt = pt4[sl];
                float4 p0 = px4[2 * sl];
                float4 p1 = px4[2 * sl + 1];
                float dt, dx, dy, r2, e;
                dt = ti - tt.x; dx = xi - p0.x; dy = yi - p0.y; r2 = dx*dx + dy*dy;
                e = __expf(-(r2 * inv2s2 + omega * dt)); s += (dt > 0.0f) ? e : 0.0f;
                dt = ti - tt.y; dx = xi - p0.z; dy = yi - p0.w; r2 = dx*dx + dy*dy;
                e = __expf(-(r2 * inv2s2 + omega * dt)); s += (dt > 0.0f) ? e : 0.0f;
                dt = ti - tt.z; dx = xi - p1.x; dy = yi - p1.y; r2 = dx*dx + dy*dy;
                e = __expf(-(r2 * inv2s2 + omega * dt)); s += (dt > 0.0f) ? e : 0.0f;
                dt = ti - tt.w; dx = xi - p1.z; dy = yi - p1.w; r2 = dx*dx + dy*dy;
                e = __expf(-(r2 * inv2s2 + omega * dt)); s += (dt > 0.0f) ? e : 0.0f;
            }
        } else {
            #pragma unroll 4
            for (int sl = lane; sl < M / 4; sl += 32) {
                float4 tt = pt4[sl];
                float4 p0 = px4[2 * sl];
                float4 p1 = px4[2 * sl + 1];
                float dt, dx, dy, r2, e;
                dt = ti - tt.x; dx = xi - p0.x; dy = yi - p0.y; r2 = dx*dx + dy*dy;
                e = __expf(-(r2 * inv2s2 + omega * dt)); s += (dt > 0.0f) ? e : 0.0f;
                dt = ti - tt.y; dx = xi - p0.z; dy = yi - p0.w; r2 = dx*dx + dy*dy;
                e = __expf(-(r2 * inv2s2 + omega * dt)); s += (dt > 0.0f) ? e : 0.0f;
                dt = ti - tt.z; dx = xi - p1.x; dy = yi - p1.y; r2 = dx*dx + dy*dy;
                e = __expf(-(r2 * inv2s2 + omega * dt)); s += (dt > 0.0f) ? e : 0.0f;
                dt = ti - tt.w; dx = xi - p1.z; dy = yi - p1.w; r2 = dx*dx + dy*dy;
                e = __expf(-(r2 * inv2s2 + omega * dt)); s += (dt > 0.0f) ? e : 0.0f;
            }
        }

        // ---- spatial grid factor A_i (x_grid is small, L1/L2 resident) ----
        float a = 0.0f;
        const float2* __restrict__ gx = reinterpret_cast<const float2*>(x_grid);
        #pragma unroll 4
        for (int g = lane; g < G; g += 32) {
            float2 p  = gx[g];
            float  dx = p.x - xi;
            float  dy = p.y - yi;
            a += __expf(-(dx * dx + dy * dy) * inv2s2);
        }

        // ---- temporal grid factor B_i ----
        float b = 0.0f;
        for (int k = lane; k < T; k += 32) {
            float dtau = t_grid[k] - ti;
            if (dtau > 0.0f)
                b += __expf(-omega * dtau);
        }

        // ---- baseline partial: lanes [0, D) ----
        float mu = 0.0f;
        if (lane < D)
            mu = cov[(size_t)i * D + lane] * beta[lane];

        // ---- warp-only deterministic reduction (s, a, b, mu) ----
        #pragma unroll
        for (int o = 16; o > 0; o >>= 1) {
            s  += __shfl_down_sync(0xffffffffu, s,  o);
            a  += __shfl_down_sync(0xffffffffu, a,  o);
            b  += __shfl_down_sync(0xffffffffu, b,  o);
            mu += __shfl_down_sync(0xffffffffu, mu, o);
        }

        if (lane == 0) {
            mu = fmaxf(mu, EPSF);
            float lam = mu + Cf * s;
            out[i]  = logf(lam + EPSF);
            g_ev[i] = a * b;
        }
        __syncthreads();   // uniform per-block before arrival protocol
    }

    // ================= last-block final reduction =================
    if (tid == 0) {
        __threadfence();
        int prev = atomicAdd(&g_count, 1);
        sm_last = (prev == (int)gridDim.x - 1) ? 1 : 0;
    }
    __syncthreads();

    if (sm_last) {
        __threadfence();   // all partials visible

        float e = 0.0f;
        for (int i2 = tid; i2 < N; i2 += TPB) e += g_ev[i2];
        float b2 = (tid < NB_BASE) ? g_base[tid] : 0.0f;

        #pragma unroll
        for (int o = 16; o > 0; o >>= 1) {
            e  += __shfl_down_sync(0xffffffffu, e, o);
            b2 += __shfl_down_sync(0xffffffffu, b2, o);
        }
        if (lane == 0) { smS[warp] = e; smB[warp] = b2; }
        __syncthreads();

        if (tid == 0) {
            float E  = smS[0] + smS[1] + smS[2] + smS[3];
            float B2 = smB[0] + smB[1] + smB[2] + smB[3];

            const float dt_step = t_grid[1] - t_grid[0];
            const float dxdy = 1.0f / (float)G;
            out[N] = (B2 + Cf * E) * dxdy * dt_step;

            g_count = 0;   // reset for next graph replay
        }
    }
}

// ---------------------------------------------------------------------------
extern "C" void kernel_launch(void* const* d_in, const int* in_sizes, int n_in,
                              void* d_out, int out_size)
{
    const float* x       = (const float*)d_in[0];
    const float* t       = (const float*)d_in[1];
    const float* past_x  = (const float*)d_in[2];
    const float* past_t  = (const float*)d_in[3];
    const float* cov     = (const float*)d_in[4];
    const float* z_grid  = (const float*)d_in[5];
    const float* x_grid  = (const float*)d_in[6];
    const float* t_grid  = (const float*)d_in[7];
    const float* beta    = (const float*)d_in[8];
    const float* p_alpha = (const float*)d_in[9];
    const float* p_sigma = (const float*)d_in[10];
    const float* p_omega = (const float*)d_in[11];
    float* out = (float*)d_out;

    const int N = in_sizes[1];
    const int M = in_sizes[3] / N;
    const int D = in_sizes[8];
    const int G = in_sizes[6] / 2;
    const int T = in_sizes[7];
    const int rows = in_sizes[5] / D;   // T*G

    const int nblk = NB_BASE + (N + EV_PER_BLK - 1) / EV_PER_BLK;

    k_fused<<<nblk, TPB>>>(x, t, past_x, past_t, cov, z_grid, x_grid,
                           t_grid, beta, p_alpha, p_sigma, p_omega,
                           N, M, G, T, D, rows, out);
}